// round 7
// baseline (speedup 1.0000x reference)
#include <cuda_runtime.h>

#define M_ROWS 12288
#define N_COLS 12288
#define D_DIM  128
#define INV_T  (1.0f/0.07f)
#define IDXCAP 128
#define SCAN_TB 256
#define SCAN_IT ((N_COLS/4)/SCAN_TB)   // 12 int4 loads per thread
#define WPB    8                       // warps (rows) per block in attn

// static scratch (allocation-free)
__device__ int g_cnt[M_ROWS];
__device__ int g_idx[(size_t)M_ROWS * IDXCAP];

// ---------------------------------------------------------------------------
// Kernel S: pure adjacency stream -> compact neighbor lists.
// Proven 84% DRAM / 6.7 TB/s. Untouched.
// ---------------------------------------------------------------------------
__global__ void __launch_bounds__(SCAN_TB) scan_kernel(const int4* __restrict__ adj4) {
    __shared__ int s_cnt;
    const int m   = blockIdx.x;
    const int tid = threadIdx.x;
    const int4* row = adj4 + (size_t)m * (N_COLS / 4);

    if (tid == 0) s_cnt = 0;

    int4 v[SCAN_IT];
    #pragma unroll
    for (int it = 0; it < SCAN_IT; it++)
        v[it] = row[it * SCAN_TB + tid];

    __syncthreads();

    int* rowidx = g_idx + (size_t)m * IDXCAP;
    #pragma unroll
    for (int it = 0; it < SCAN_IT; it++) {
        if (v[it].x | v[it].y | v[it].z | v[it].w) {
            int base = (it * SCAN_TB + tid) * 4;
            if (v[it].x) { int p = atomicAdd(&s_cnt, 1); if (p < IDXCAP) rowidx[p] = base;     }
            if (v[it].y) { int p = atomicAdd(&s_cnt, 1); if (p < IDXCAP) rowidx[p] = base + 1; }
            if (v[it].z) { int p = atomicAdd(&s_cnt, 1); if (p < IDXCAP) rowidx[p] = base + 2; }
            if (v[it].w) { int p = atomicAdd(&s_cnt, 1); if (p < IDXCAP) rowidx[p] = base + 3; }
        }
    }
    __syncthreads();
    if (tid == 0) g_cnt[m] = min(s_cnt, IDXCAP);
}

// ---------------------------------------------------------------------------
// Kernel C v4: ONE WARP PER ROW, zero block barriers.
//   1. matvec b = x_anchor[m] @ W  in-warp (W via L1-hot LDG.128), b stays
//      in registers (one float4/lane) -- the xw kernel and g_xa are gone.
//   2. scores: warp-coalesced float4 gathers + shuffle-reduce dots.
//   3. online softmax over tiles of 32 (exact: masked terms exp to 0).
//   4. aggregation: shuffle-broadcast weights, L1-hit re-gathers.
// ---------------------------------------------------------------------------
__global__ void __launch_bounds__(WPB * 32) attn_fused(const float4* __restrict__ xin4,
                                                       const float4* __restrict__ xanchor4,
                                                       const float4* __restrict__ W4,
                                                       float4*       __restrict__ out4) {
    __shared__ float s_x[WPB][D_DIM];

    const int warp = threadIdx.x >> 5;
    const int lane = threadIdx.x & 31;
    const int m    = blockIdx.x * WPB + warp;
    const unsigned FULL = 0xffffffffu;

    // ---- anchor row -> per-warp smem (512B), then matvec b = x @ W ----
    {
        float4 xv = xanchor4[(size_t)m * 32 + lane];
        reinterpret_cast<float4*>(&s_x[warp][0])[lane] = xv;
    }
    __syncwarp();

    float4 b = make_float4(0.f, 0.f, 0.f, 0.f);
    #pragma unroll 8
    for (int d4 = 0; d4 < 32; d4++) {
        const float4 xb = reinterpret_cast<const float4*>(&s_x[warp][0])[d4]; // broadcast
        float4 w0 = W4[(size_t)(d4 * 4 + 0) * 32 + lane];
        float4 w1 = W4[(size_t)(d4 * 4 + 1) * 32 + lane];
        float4 w2 = W4[(size_t)(d4 * 4 + 2) * 32 + lane];
        float4 w3 = W4[(size_t)(d4 * 4 + 3) * 32 + lane];
        b.x += xb.x * w0.x; b.y += xb.x * w0.y; b.z += xb.x * w0.z; b.w += xb.x * w0.w;
        b.x += xb.y * w1.x; b.y += xb.y * w1.y; b.z += xb.y * w1.z; b.w += xb.y * w1.w;
        b.x += xb.z * w2.x; b.y += xb.z * w2.y; b.z += xb.z * w2.z; b.w += xb.z * w2.w;
        b.x += xb.w * w3.x; b.y += xb.w * w3.y; b.z += xb.w * w3.z; b.w += xb.w * w3.w;
    }

    const int cnt = g_cnt[m];

    if (cnt == 0) {
        // all-masked row: uniform softmax -> column mean (P ~ 2e-11, correctness only)
        float4 acc = make_float4(0.f, 0.f, 0.f, 0.f);
        for (int n = 0; n < N_COLS; n++) {
            float4 a = xin4[(size_t)n * 32 + lane];
            acc.x += a.x; acc.y += a.y; acc.z += a.z; acc.w += a.w;
        }
        const float s = 1.0f / N_COLS;
        acc.x *= s; acc.y *= s; acc.z *= s; acc.w *= s;
        out4[(size_t)m * 32 + lane] = acc;
        return;
    }

    // ---- online softmax + aggregation over tiles of 32 neighbors ----
    float  mrun = -3.0e38f;
    float  lrun = 0.f;
    float4 acc  = make_float4(0.f, 0.f, 0.f, 0.f);

    for (int t = 0; t * 32 < cnt; t++) {
        const int tlen = min(32, cnt - t * 32);
        int myidx = 0;
        if (lane < tlen)
            myidx = g_idx[(size_t)m * IDXCAP + t * 32 + lane];

        // scores: warp-cooperative dot per neighbor; score k parked in lane k
        float pk = -3.0e38f;
        #pragma unroll
        for (int k = 0; k < 32; k++) {
            if (k < tlen) {
                const int n = __shfl_sync(FULL, myidx, k);
                float4 a = xin4[(size_t)n * 32 + lane];
                float p = fmaf(a.x, b.x, fmaf(a.y, b.y, fmaf(a.z, b.z, a.w * b.w)));
                #pragma unroll
                for (int o = 16; o; o >>= 1) p += __shfl_xor_sync(FULL, p, o);
                if (lane == k) pk = p;
            }
        }

        // tile max + online rescale (all-shuffle, no barriers)
        float tmax = pk;
        #pragma unroll
        for (int o = 16; o; o >>= 1) tmax = fmaxf(tmax, __shfl_xor_sync(FULL, tmax, o));
        const float mnew  = fmaxf(mrun, tmax);
        const float scale = __expf((mrun - mnew) * INV_T);   // 0 on first tile
        float ek = (lane < tlen) ? __expf((pk - mnew) * INV_T) : 0.f;
        float tsum = ek;
        #pragma unroll
        for (int o = 16; o; o >>= 1) tsum += __shfl_xor_sync(FULL, tsum, o);
        lrun = lrun * scale + tsum;
        mrun = mnew;
        acc.x *= scale; acc.y *= scale; acc.z *= scale; acc.w *= scale;

        // aggregation: broadcast e_k, re-gather row (L1 hit)
        #pragma unroll
        for (int k = 0; k < 32; k++) {
            if (k < tlen) {
                const float w = __shfl_sync(FULL, ek, k);
                const int   n = __shfl_sync(FULL, myidx, k);
                float4 a = xin4[(size_t)n * 32 + lane];
                acc.x += w * a.x; acc.y += w * a.y; acc.z += w * a.z; acc.w += w * a.w;
            }
        }
    }

    const float inv = 1.0f / lrun;
    acc.x *= inv; acc.y *= inv; acc.z *= inv; acc.w *= inv;
    out4[(size_t)m * 32 + lane] = acc;
}

// ---------------------------------------------------------------------------
// inputs: 0=xx_anchor [12288,128] f32, 1=input [12288,128] f32,
//         2=adj [12288,12288] i32,    3=weight [128,128] f32
// output: [12288,128] f32
//
// Serial two-kernel pipeline (stream overlap proven harmful on this workload:
// the adj stream at the DRAM cap loses more to interference than overlap
// saves -- R3/R5 evidence).
// ---------------------------------------------------------------------------
extern "C" void kernel_launch(void* const* d_in, const int* in_sizes, int n_in,
                              void* d_out, int out_size) {
    const float* xx_anchor = (const float*)d_in[0];
    const float* input     = (const float*)d_in[1];
    const int*   adj       = (const int*)  d_in[2];
    const float* weight    = (const float*)d_in[3];
    float*       out       = (float*)d_out;

    scan_kernel<<<M_ROWS, SCAN_TB>>>((const int4*)adj);
    attn_fused<<<M_ROWS / WPB, WPB * 32>>>((const float4*)input,
                                           (const float4*)xx_anchor,
                                           (const float4*)weight,
                                           (float4*)out);
}

// round 8
// speedup vs baseline: 1.2696x; 1.2696x over previous
#include <cuda_runtime.h>

#define M_ROWS 12288
#define N_COLS 12288
#define D_DIM  128
#define INV_T  (1.0f/0.07f)
#define IDXCAP 128
#define NCACHE 32
#define SCAN_TB 256
#define SCAN_IT ((N_COLS/4)/SCAN_TB)   // 12 int4 loads per thread
#define A_ROWS 32

// static scratch (allocation-free)
__device__ float g_xa[(size_t)M_ROWS * D_DIM];
__device__ int   g_cnt[M_ROWS];
__device__ int   g_idx[(size_t)M_ROWS * IDXCAP];

// ---------------------------------------------------------------------------
// Kernel A: g_xa = X @ W  (proven 19.3us; W in registers, reused for 32 rows)
// ---------------------------------------------------------------------------
__global__ void __launch_bounds__(128) xw_kernel(const float* __restrict__ X,
                                                 const float* __restrict__ W) {
    __shared__ float Xs[A_ROWS][D_DIM];
    const int e    = threadIdx.x;
    const int row0 = blockIdx.x * A_ROWS;

    for (int r = 0; r < A_ROWS; r++)
        Xs[r][e] = X[(size_t)(row0 + r) * D_DIM + e];

    float wreg[D_DIM];
    #pragma unroll
    for (int d = 0; d < D_DIM; d++)
        wreg[d] = W[d * D_DIM + e];
    __syncthreads();

    for (int r = 0; r < A_ROWS; r++) {
        const float4* x4 = reinterpret_cast<const float4*>(&Xs[r][0]);
        float s0 = 0.f, s1 = 0.f;
        #pragma unroll
        for (int q = 0; q < D_DIM / 4; q++) {
            float4 xv = x4[q];
            s0 += xv.x * wreg[4*q + 0];
            s1 += xv.y * wreg[4*q + 1];
            s0 += xv.z * wreg[4*q + 2];
            s1 += xv.w * wreg[4*q + 3];
        }
        g_xa[(size_t)(row0 + r) * D_DIM + e] = s0 + s1;
    }
}

// ---------------------------------------------------------------------------
// Kernel S: pure adjacency stream -> compact neighbor lists.
// Proven 84% DRAM / 6.7 TB/s. FULL grid -- never chunk (R3/R5 evidence).
// ---------------------------------------------------------------------------
__global__ void __launch_bounds__(SCAN_TB) scan_kernel(const int4* __restrict__ adj4) {
    __shared__ int s_cnt;
    const int m   = blockIdx.x;
    const int tid = threadIdx.x;
    const int4* row = adj4 + (size_t)m * (N_COLS / 4);

    if (tid == 0) s_cnt = 0;

    int4 v[SCAN_IT];
    #pragma unroll
    for (int it = 0; it < SCAN_IT; it++)
        v[it] = row[it * SCAN_TB + tid];

    __syncthreads();

    int* rowidx = g_idx + (size_t)m * IDXCAP;
    #pragma unroll
    for (int it = 0; it < SCAN_IT; it++) {
        if (v[it].x | v[it].y | v[it].z | v[it].w) {
            int base = (it * SCAN_TB + tid) * 4;
            if (v[it].x) { int p = atomicAdd(&s_cnt, 1); if (p < IDXCAP) rowidx[p] = base;     }
            if (v[it].y) { int p = atomicAdd(&s_cnt, 1); if (p < IDXCAP) rowidx[p] = base + 1; }
            if (v[it].z) { int p = atomicAdd(&s_cnt, 1); if (p < IDXCAP) rowidx[p] = base + 2; }
            if (v[it].w) { int p = atomicAdd(&s_cnt, 1); if (p < IDXCAP) rowidx[p] = base + 3; }
        }
    }
    __syncthreads();
    if (tid == 0) g_cnt[m] = min(s_cnt, IDXCAP);
}

// ---------------------------------------------------------------------------
// Kernel C (proven v2, 29us): gather-once smem row cache + fused scores,
// block softmax, aggregation.
// ---------------------------------------------------------------------------
__global__ void __launch_bounds__(128) attn_compute(const float* __restrict__ xin,
                                                    float*       __restrict__ out) {
    __shared__ float s_rows[NCACHE][D_DIM];
    __shared__ float s_xa[D_DIM];
    __shared__ int   s_idx[IDXCAP];
    __shared__ float s_val[IDXCAP];
    __shared__ float s_sum;

    const int m    = blockIdx.x;
    const int tid  = threadIdx.x;
    const int wid  = tid >> 5;
    const int lane = tid & 31;

    const int cnt = g_cnt[m];
    s_xa[tid] = g_xa[(size_t)m * D_DIM + tid];
    if (tid < cnt) s_idx[tid] = g_idx[(size_t)m * IDXCAP + tid];
    __syncthreads();

    if (cnt == 0) {
        float acc = 0.f;
        for (int n = 0; n < N_COLS; n++)
            acc += xin[(size_t)n * D_DIM + tid];
        out[(size_t)m * D_DIM + tid] = acc * (1.0f / N_COLS);
        return;
    }

    const int nc = min(cnt, NCACHE);
    const float4 b = reinterpret_cast<const float4*>(s_xa)[lane];

    for (int k = wid; k < nc; k += 4) {
        const float4* r = reinterpret_cast<const float4*>(xin)
                        + (size_t)s_idx[k] * (D_DIM / 4);
        float4 a = r[lane];
        reinterpret_cast<float4*>(&s_rows[k][0])[lane] = a;
        float p = a.x * b.x + a.y * b.y + a.z * b.z + a.w * b.w;
        #pragma unroll
        for (int o = 16; o; o >>= 1) p += __shfl_xor_sync(0xffffffffu, p, o);
        if (lane == 0) s_val[k] = p;
    }
    for (int k = NCACHE + wid; k < cnt; k += 4) {
        const float4* r = reinterpret_cast<const float4*>(xin)
                        + (size_t)s_idx[k] * (D_DIM / 4);
        float4 a = r[lane];
        float p = a.x * b.x + a.y * b.y + a.z * b.z + a.w * b.w;
        #pragma unroll
        for (int o = 16; o; o >>= 1) p += __shfl_xor_sync(0xffffffffu, p, o);
        if (lane == 0) s_val[k] = p;
    }
    __syncthreads();

    if (wid == 0) {
        float mx = -3.0e38f;
        for (int k = lane; k < cnt; k += 32) mx = fmaxf(mx, s_val[k]);
        #pragma unroll
        for (int o = 16; o; o >>= 1) mx = fmaxf(mx, __shfl_xor_sync(0xffffffffu, mx, o));
        float sm = 0.f;
        for (int k = lane; k < cnt; k += 32) {
            float e = __expf((s_val[k] - mx) * INV_T);
            s_val[k] = e;
            sm += e;
        }
        #pragma unroll
        for (int o = 16; o; o >>= 1) sm += __shfl_xor_sync(0xffffffffu, sm, o);
        if (lane == 0) s_sum = sm;
    }
    __syncthreads();

    float acc = 0.f;
    for (int k = 0; k < nc; k++)
        acc += s_val[k] * s_rows[k][tid];
    for (int k = nc; k < cnt; k++)
        acc += s_val[k] * xin[(size_t)s_idx[k] * D_DIM + tid];
    out[(size_t)m * D_DIM + tid] = acc / s_sum;
}

// ---------------------------------------------------------------------------
// inputs: 0=xx_anchor [12288,128] f32, 1=input [12288,128] f32,
//         2=adj [12288,12288] i32,    3=weight [128,128] f32
// output: [12288,128] f32
//
// Capture path: xw (4% DRAM, ~12MB traffic) forked alongside the FULL
// unchunked scan (84% DRAM). This exact topology never ran before: R4 had it
// but its probe provably failed; R5 fixed the probe but chunked the scan
// (regression came from chunk wave-tails + attn interference, not xw).
// Join both, then attn. Serial fallback otherwise -- floor 139.3us.
// ---------------------------------------------------------------------------
extern "C" void kernel_launch(void* const* d_in, const int* in_sizes, int n_in,
                              void* d_out, int out_size) {
    const float* xx_anchor = (const float*)d_in[0];
    const float* input     = (const float*)d_in[1];
    const int*   adj       = (const int*)  d_in[2];
    const float* weight    = (const float*)d_in[3];
    float*       out       = (float*)d_out;
    const int4*  adj4      = (const int4*)adj;

    // find the capturing stream among all default-stream aliases (R5-proven)
    cudaStream_t cap = 0;
    bool capturing = false;
    cudaStream_t cands[3] = { (cudaStream_t)0, cudaStreamPerThread, cudaStreamLegacy };
    for (int i = 0; i < 3 && !capturing; i++) {
        cudaStreamCaptureStatus st = cudaStreamCaptureStatusNone;
        if (cudaStreamIsCapturing(cands[i], &st) == cudaSuccess &&
            st == cudaStreamCaptureStatusActive) {
            cap = cands[i];
            capturing = true;
        }
        (void)cudaGetLastError();
    }

    if (capturing) {
        int loPri = 0, hiPri = 0;
        (void)cudaDeviceGetStreamPriorityRange(&loPri, &hiPri);
        cudaStream_t s2 = 0;
        cudaEvent_t evF = 0, evJ = 0;
        bool ok = (cudaStreamCreateWithPriority(&s2, cudaStreamNonBlocking, loPri)
                   == cudaSuccess);
        if (ok) ok = (cudaEventCreateWithFlags(&evF, cudaEventDisableTiming) == cudaSuccess);
        if (ok) ok = (cudaEventCreateWithFlags(&evJ, cudaEventDisableTiming) == cudaSuccess);
        if (ok) ok = (cudaEventRecord(evF, cap) == cudaSuccess);
        if (ok) ok = (cudaStreamWaitEvent(s2, evF, 0) == cudaSuccess);

        if (ok) {
            xw_kernel<<<M_ROWS / A_ROWS, 128, 0, s2>>>(xx_anchor, weight); // hidden
            scan_kernel<<<M_ROWS, SCAN_TB, 0, cap>>>(adj4);                // full stream
            cudaEventRecord(evJ, s2);
            cudaStreamWaitEvent(cap, evJ, 0);                              // join
            attn_compute<<<M_ROWS, 128, 0, cap>>>(input, out);
            return;
        }
        (void)cudaGetLastError();
        // fall through to serial
    }

    // serial path (correctness runs / probe failure) -- proven 139.3us
    scan_kernel<<<M_ROWS, SCAN_TB>>>(adj4);
    xw_kernel<<<M_ROWS / A_ROWS, 128>>>(xx_anchor, weight);
    attn_compute<<<M_ROWS, 128>>>(input, out);
}